// round 2
// baseline (speedup 1.0000x reference)
#include <cuda_runtime.h>

// QConv2d: new_rho[b] = U2 @ rho[b] @ U2^T, U2 = (uc[:,2:4]) ⊗ ux ⊗ uy
// Factored (separable) evaluation, fp32 exact.
//
// Layout: index p = c*64 + x*8 + y  (c in {0,1} input / {0..3} output)
// Steps (in-place on 128x128 smem tile A, A[pl*128 + pr]):
//   S0: uy on right-y   (stride 1)
//   S1: ux on right-x   (stride 8)
//   S2: uy on left-y    (stride 128)
//   S3: ux on left-x    (stride 1024)
// Final: fused uc on both sides + coalesced gmem store.

#define NT 256
#define SMEM_FLOATS (16384 + 136)
#define SMEM_BYTES  (SMEM_FLOATS * 4)

template <int MODE>
__device__ __forceinline__ void stepT(float* __restrict__ A,
                                      const float* __restrict__ Usm,
                                      int tid)
{
    // Hoist the 8x8 factor into registers (shared-broadcast loads, once per step).
    float Ur[64];
#pragma unroll
    for (int i = 0; i < 64; i++) Ur[i] = Usm[i];

#pragma unroll
    for (int it = 0; it < 2048 / NT; it++) {
        const int run = tid + it * NT;
        int base, stride, s;
        if (MODE == 0) {            // uy, right side: contiguous runs
            base = (run >> 4) * 128 + (run & 15) * 8;
            stride = 1;
            s = (run >> 2) & 7;     // bank-conflict-avoiding xor swizzle
        } else if (MODE == 1) {     // ux, right side: stride 8
            base = (run >> 4) * 128 + ((run >> 3) & 1) * 64 + (run & 7);
            stride = 8;
            s = (run >> 3) & 3;
        } else if (MODE == 2) {     // uy, left side: stride 128 (lanes over pr -> conflict-free)
            base = (run >> 7) * 1024 + (run & 127);
            stride = 128;
            s = 0;
        } else {                    // ux, left side: stride 1024
            const int t = run >> 7; // t = cl*8 + yl
            base = ((t >> 3) * 64 + (t & 7)) * 128 + (run & 127);
            stride = 1024;
            s = 0;
        }

        float v[8];
#pragma unroll
        for (int i = 0; i < 8; i++) {
            const int k = i ^ s;
            v[k] = A[base + k * stride];
        }
        float a[8];
#pragma unroll
        for (int ko = 0; ko < 8; ko++) {
            float acc = Ur[ko * 8] * v[0];
#pragma unroll
            for (int k = 1; k < 8; k++) acc = fmaf(Ur[ko * 8 + k], v[k], acc);
            a[ko] = acc;
        }
#pragma unroll
        for (int i = 0; i < 8; i++) {
            const int k = i ^ s;
            A[base + k * stride] = a[k];
        }
    }
}

__global__ __launch_bounds__(NT, 2)
void qconv_kernel(const float* __restrict__ rho,
                  const float* __restrict__ gux,
                  const float* __restrict__ guy,
                  const float* __restrict__ guc,
                  float* __restrict__ out)
{
    extern __shared__ float sm[];
    float* A  = sm;          // 16384 floats: the 128x128 working tile
    float* sU = sm + 16384;  // [0:64) uy, [64:128) ux, [128:136) wc[c'][c] = uc[c', c+2]

    const int tid = threadIdx.x;
    const int b   = blockIdx.x;

    // ---- load rho[b] (64 KB, coalesced float4) ----
    {
        const float4* src = (const float4*)(rho + (long)b * 16384);
        float4* dst = (float4*)A;
#pragma unroll
        for (int i = 0; i < 4096 / NT; i++)
            dst[tid + i * NT] = src[tid + i * NT];
    }
    if (tid < 64) {
        sU[tid] = guy[tid];
    } else if (tid < 128) {
        sU[tid] = gux[tid - 64];
    } else if (tid < 136) {
        const int i = tid - 128;                 // i = c'*2 + c
        sU[128 + i] = guc[(i >> 1) * 4 + (i & 1) + 2];
    }
    __syncthreads();

    stepT<0>(A, sU,      tid); __syncthreads();  // uy right
    stepT<1>(A, sU + 64, tid); __syncthreads();  // ux right
    stepT<2>(A, sU,      tid); __syncthreads();  // uy left
    stepT<3>(A, sU + 64, tid); __syncthreads();  // ux left

    // ---- fused channel expansion on both sides + store ----
    float wc[8];
#pragma unroll
    for (int i = 0; i < 8; i++) wc[i] = sU[128 + i];

    float4* outb = (float4*)(out + (long)b * 65536);
    const float4* Af = (const float4*)A;

#pragma unroll
    for (int it = 0; it < 1024 / NT; it++) {
        const int item = tid + it * NT;
        const int irv = item & 15;   // ir = irv*4 (right pixel index / 4)
        const int il  = item >> 4;   // left pixel index, 0..63

        const float4 m00 = Af[il * 32 + irv];             // cl=0, cr=0
        const float4 m01 = Af[il * 32 + 16 + irv];        // cl=0, cr=1
        const float4 m10 = Af[(64 + il) * 32 + irv];      // cl=1, cr=0
        const float4 m11 = Af[(64 + il) * 32 + 16 + irv]; // cl=1, cr=1

#pragma unroll
        for (int cpr = 0; cpr < 4; cpr++) {
            const float w0 = wc[cpr * 2], w1 = wc[cpr * 2 + 1];
            float4 t0, t1;
            t0.x = fmaf(w1, m01.x, w0 * m00.x);
            t0.y = fmaf(w1, m01.y, w0 * m00.y);
            t0.z = fmaf(w1, m01.z, w0 * m00.z);
            t0.w = fmaf(w1, m01.w, w0 * m00.w);
            t1.x = fmaf(w1, m11.x, w0 * m10.x);
            t1.y = fmaf(w1, m11.y, w0 * m10.y);
            t1.z = fmaf(w1, m11.z, w0 * m10.z);
            t1.w = fmaf(w1, m11.w, w0 * m10.w);
#pragma unroll
            for (int cpl = 0; cpl < 4; cpl++) {
                const float v0 = wc[cpl * 2], v1 = wc[cpl * 2 + 1];
                float4 o;
                o.x = fmaf(v1, t1.x, v0 * t0.x);
                o.y = fmaf(v1, t1.y, v0 * t0.y);
                o.z = fmaf(v1, t1.z, v0 * t0.z);
                o.w = fmaf(v1, t1.w, v0 * t0.w);
                // out row p' = cpl*64 + il, cols [cpr*64 + 4*irv .. +3]
                outb[(cpl * 64 + il) * 64 + cpr * 16 + irv] = o;
            }
        }
    }
}

extern "C" void kernel_launch(void* const* d_in, const int* in_sizes, int n_in,
                              void* d_out, int out_size)
{
    const float* rho = (const float*)d_in[0];
    const float* ux  = (const float*)d_in[1];
    const float* uy  = (const float*)d_in[2];
    const float* uc  = (const float*)d_in[3];
    float* out = (float*)d_out;

    const int B = in_sizes[0] / 16384;  // batches (rho is [B,128,128])

    cudaFuncSetAttribute(qconv_kernel,
                         cudaFuncAttributeMaxDynamicSharedMemorySize, SMEM_BYTES);
    qconv_kernel<<<B, NT, SMEM_BYTES>>>(rho, ux, uy, uc, out);
}

// round 4
// speedup vs baseline: 2.4924x; 2.4924x over previous
#include <cuda_runtime.h>

// QConv2d: new_rho[b] = U2 @ rho[b] @ U2^T, U2 = uc[:,2:4] ⊗ ux ⊗ uy
// Register-resident separable evaluation.
//
// smem tile A: 128 rows x 136 words. Row r = [64 floats | 4 pad | 64 floats | 4 pad]
// (half offset 68 -> conflict-free LDS/STS.128 on rows AND stride-1 lanes on columns).
//
// P1: gmem -> smem (coalesced)                P2: per-thread row-half transform (regs)
// P3: per-thread column-half transform (regs) P4: fused uc on both sides + stores.
// All phases keep the HO-padded layout; P3 read-set == write-set per thread,
// so no barrier is needed between its load and store.

#define NT 256
#define RS 136        // row stride in floats
#define HO 68         // second-half offset
#define SMEM_WORDS (128 * RS + 136)
#define SMEM_BYTES (SMEM_WORDS * 4)

__device__ __forceinline__ void transform64(float* __restrict__ d,
                                            const float4* __restrict__ Uy4,
                                            const float4* __restrict__ Ux4)
{
    // uy pass: 8 contiguous groups (x fixed), in-place per group
#pragma unroll
    for (int x = 0; x < 8; x++) {
        float v[8];
#pragma unroll
        for (int k = 0; k < 8; k++) v[k] = d[x * 8 + k];
#pragma unroll
        for (int yo = 0; yo < 8; yo++) {
            const float4 ua = Uy4[yo * 2], ub = Uy4[yo * 2 + 1];
            float acc =      ua.x * v[0];
            acc = fmaf(ua.y, v[1], acc);
            acc = fmaf(ua.z, v[2], acc);
            acc = fmaf(ua.w, v[3], acc);
            acc = fmaf(ub.x, v[4], acc);
            acc = fmaf(ub.y, v[5], acc);
            acc = fmaf(ub.z, v[6], acc);
            acc = fmaf(ub.w, v[7], acc);
            d[x * 8 + yo] = acc;
        }
    }
    // ux pass: stride-8 groups (y fixed), in-place per group
#pragma unroll
    for (int y = 0; y < 8; y++) {
        float v[8];
#pragma unroll
        for (int k = 0; k < 8; k++) v[k] = d[k * 8 + y];
#pragma unroll
        for (int xo = 0; xo < 8; xo++) {
            const float4 ua = Ux4[xo * 2], ub = Ux4[xo * 2 + 1];
            float acc =      ua.x * v[0];
            acc = fmaf(ua.y, v[1], acc);
            acc = fmaf(ua.z, v[2], acc);
            acc = fmaf(ua.w, v[3], acc);
            acc = fmaf(ub.x, v[4], acc);
            acc = fmaf(ub.y, v[5], acc);
            acc = fmaf(ub.z, v[6], acc);
            acc = fmaf(ub.w, v[7], acc);
            d[xo * 8 + y] = acc;
        }
    }
}

__global__ __launch_bounds__(NT, 2)
void qconv_kernel(const float* __restrict__ rho,
                  const float* __restrict__ gux,
                  const float* __restrict__ guy,
                  const float* __restrict__ guc,
                  float* __restrict__ out)
{
    extern __shared__ float sm[];
    float* A  = sm;               // 128 x 136 (HO-padded)
    float* sU = sm + 128 * RS;    // [0:64) uy, [64:128) ux, [128:136) wc

    const int tid = threadIdx.x;
    const int b   = blockIdx.x;

    // ---- P1: load rho[b] (coalesced float4) into padded layout ----
    {
        const float4* src = (const float4*)(rho + (long)b * 16384);
#pragma unroll
        for (int i = 0; i < 16; i++) {
            const int g = tid + i * NT;
            const float4 v = src[g];
            const int word = g * 4;
            const int r = word >> 7, rem = word & 127;
            const int sw = r * RS + (rem >> 6) * HO + (rem & 63);
            *(float4*)(A + sw) = v;
        }
    }
    if (tid < 64) {
        sU[tid] = guy[tid];
    } else if (tid < 128) {
        sU[tid] = gux[tid - 64];
    } else if (tid < 136) {
        const int i = tid - 128;                  // i = c'*2 + c
        sU[128 + i] = guc[(i >> 1) * 4 + (i & 1) + 2];
    }
    __syncthreads();

    const float4* Uy4 = (const float4*)sU;
    const float4* Ux4 = (const float4*)(sU + 64);

    // ---- P2: right-side transform, one row-half per thread ----
    {
        const int r = tid >> 1, h = tid & 1;
        float* base = A + r * RS + h * HO;
        float d[64];
#pragma unroll
        for (int i = 0; i < 16; i++) {
            const float4 v = *(const float4*)(base + 4 * i);
            d[4 * i] = v.x; d[4 * i + 1] = v.y; d[4 * i + 2] = v.z; d[4 * i + 3] = v.w;
        }
        transform64(d, Uy4, Ux4);
#pragma unroll
        for (int i = 0; i < 16; i++)
            *(float4*)(base + 4 * i) =
                make_float4(d[4 * i], d[4 * i + 1], d[4 * i + 2], d[4 * i + 3]);
    }
    __syncthreads();

    // ---- P3: left-side transform, one column-half per thread ----
    // Read-set == write-set per thread (register-resident in between), so no
    // extra barrier between load and store.
    {
        const int cl = tid >> 7;          // left-channel half (rows [cl*64, cl*64+64))
        const int c  = tid & 127;         // column pr
        const int off = cl * 64 * RS + (c >> 6) * HO + (c & 63);
        float d[64];
#pragma unroll
        for (int i = 0; i < 64; i++) d[i] = A[off + i * RS];   // lanes stride-1: conflict-free
        transform64(d, Uy4, Ux4);
#pragma unroll
        for (int i = 0; i < 64; i++) A[off + i * RS] = d[i];   // same addresses back
    }
    __syncthreads();

    // ---- P4: fused channel expansion on both sides + coalesced store ----
    float wc[8];
#pragma unroll
    for (int i = 0; i < 8; i++) wc[i] = sU[128 + i];

    float4* outb = (float4*)(out + (long)b * 65536);
    const float4* Af = (const float4*)A;   // row stride RS/4 = 34 float4s; half 2 at +17

#pragma unroll
    for (int it = 0; it < 4; it++) {
        const int item = tid + it * NT;
        const int irv = item & 15;         // right pixel / 4
        const int il  = item >> 4;         // left pixel, 0..63

        const float4 m00 = Af[il * 34 + irv];              // cl=0, cr=0
        const float4 m01 = Af[il * 34 + 17 + irv];         // cl=0, cr=1 (HO half)
        const float4 m10 = Af[(64 + il) * 34 + irv];       // cl=1, cr=0
        const float4 m11 = Af[(64 + il) * 34 + 17 + irv];  // cl=1, cr=1

#pragma unroll
        for (int cpr = 0; cpr < 4; cpr++) {
            const float w0 = wc[cpr * 2], w1 = wc[cpr * 2 + 1];
            float4 t0, t1;
            t0.x = fmaf(w1, m01.x, w0 * m00.x);
            t0.y = fmaf(w1, m01.y, w0 * m00.y);
            t0.z = fmaf(w1, m01.z, w0 * m00.z);
            t0.w = fmaf(w1, m01.w, w0 * m00.w);
            t1.x = fmaf(w1, m11.x, w0 * m10.x);
            t1.y = fmaf(w1, m11.y, w0 * m10.y);
            t1.z = fmaf(w1, m11.z, w0 * m10.z);
            t1.w = fmaf(w1, m11.w, w0 * m10.w);
#pragma unroll
            for (int cpl = 0; cpl < 4; cpl++) {
                const float v0 = wc[cpl * 2], v1 = wc[cpl * 2 + 1];
                float4 o;
                o.x = fmaf(v1, t1.x, v0 * t0.x);
                o.y = fmaf(v1, t1.y, v0 * t0.y);
                o.z = fmaf(v1, t1.z, v0 * t0.z);
                o.w = fmaf(v1, t1.w, v0 * t0.w);
                outb[(cpl * 64 + il) * 64 + cpr * 16 + irv] = o;
            }
        }
    }
}

extern "C" void kernel_launch(void* const* d_in, const int* in_sizes, int n_in,
                              void* d_out, int out_size)
{
    const float* rho = (const float*)d_in[0];
    const float* ux  = (const float*)d_in[1];
    const float* uy  = (const float*)d_in[2];
    const float* uc  = (const float*)d_in[3];
    float* out = (float*)d_out;

    const int B = in_sizes[0] / 16384;

    cudaFuncSetAttribute(qconv_kernel,
                         cudaFuncAttributeMaxDynamicSharedMemorySize, SMEM_BYTES);
    qconv_kernel<<<B, NT, SMEM_BYTES>>>(rho, ux, uy, uc, out);
}